// round 12
// baseline (speedup 1.0000x reference)
#include <cuda_runtime.h>
#include <cuda_fp16.h>
#include <cstdint>
#include <math.h>

#define N_TOK   8192
#define D_MODEL 1024
#define N_EXP   8
#define RANK    16
#define H_COLS  128
#define K2      (D_MODEL + H_COLS)   // 1152 concatenated K

// ---------------- device scratch (no-alloc rule) ----------------
__device__ __align__(16) __half g_xe[N_TOK * K2];        // [x | c*h] fp16, row stride 1152
__device__ __align__(16) __half g_w2[D_MODEL * K2];      // [Wbase^T ; B] fp16: row d, col k
__device__ __align__(16) __half g_at[H_COLS * D_MODEL];  // A^T fp16: [er][d]
__device__ __align__(16) float  g_c[N_TOK * N_EXP];      // dense combine weights

// ---------------- asm helpers (legal at compute_103) ----------------
__device__ __forceinline__ uint32_t smem_u32(const void* p) {
    uint32_t a;
    asm("{ .reg .u64 t; cvta.to.shared.u64 t, %1; cvt.u32.u64 %0, t; }" : "=r"(a) : "l"(p));
    return a;
}
__device__ __forceinline__ void cp16(uint32_t s, const void* g) {
    asm volatile("cp.async.cg.shared.global [%0], [%1], 16;" :: "r"(s), "l"(g));
}
__device__ __forceinline__ void cp_commit() {
    asm volatile("cp.async.commit_group;" ::: "memory");
}
template<int N> __device__ __forceinline__ void cp_wait() {
    asm volatile("cp.async.wait_group %0;" :: "n"(N) : "memory");
}
__device__ __forceinline__ void ldm4(uint32_t (&r)[4], uint32_t a) {
    asm volatile("ldmatrix.sync.aligned.m8n8.x4.shared.b16 {%0,%1,%2,%3}, [%4];"
        : "=r"(r[0]), "=r"(r[1]), "=r"(r[2]), "=r"(r[3]) : "r"(a));
}
__device__ __forceinline__ void mma16816(float* c, const uint32_t* a, const uint32_t* b) {
    asm volatile("mma.sync.aligned.m16n8k16.row.col.f32.f16.f16.f32 "
        "{%0,%1,%2,%3}, {%4,%5,%6,%7}, {%8,%9}, {%0,%1,%2,%3};"
        : "+f"(c[0]), "+f"(c[1]), "+f"(c[2]), "+f"(c[3])
        : "r"(a[0]), "r"(a[1]), "r"(a[2]), "r"(a[3]), "r"(b[0]), "r"(b[1]));
}
__device__ __forceinline__ uint32_t h2u(__half2 h) { return *reinterpret_cast<uint32_t*>(&h); }

// 128B-row swizzle (64 halves/row, 8 x 16B chunks): chunk' = c ^ (r&7)
#define SW64(r, c) ((uint32_t)((r) * 128 + (((c) ^ ((r) & 7)) << 4)))

// ---------------------------------------------------------------------------
// Merged pack: blocks [0, 256) = fused x->fp16 + fp32 gate;
//              blocks [256, 256+5120) = weight conversion (w2 + at)
// ---------------------------------------------------------------------------
#define GATE_BLOCKS 256
#define W2_ELEMS (D_MODEL * K2)                    // 1179648
#define AT_ELEMS (H_COLS * D_MODEL)                // 131072
#define WPACK_BLOCKS ((W2_ELEMS + AT_ELEMS) / 256) // 5120

__global__ __launch_bounds__(256)
void pack_all(const float* __restrict__ x, const float* __restrict__ Wg,
              const float* __restrict__ Wb, const float* __restrict__ Bmat,
              const float* __restrict__ A) {
    const int tid = threadIdx.x;

    if (blockIdx.x >= GATE_BLOCKS) {
        // ---- weight pack path ----
        int idx = (blockIdx.x - GATE_BLOCKS) * 256 + tid;
        if (idx < W2_ELEMS) {
            int d = idx / K2, k = idx - d * K2;
            float v = (k < D_MODEL) ? Wb[(size_t)d * D_MODEL + k]
                                    : Bmat[(size_t)(k - D_MODEL) * D_MODEL + d];
            g_w2[idx] = __float2half_rn(v);
        } else {
            int t = idx - W2_ELEMS;
            int er = t >> 10, d = t & 1023;
            int e = er >> 4, r = er & 15;
            g_at[t] = __float2half_rn(A[((size_t)e * D_MODEL + d) * RANK + r]);
        }
        return;
    }

    // ---- gate path: 32 tokens per block ----
    __shared__ float sWg[N_EXP][D_MODEL];          // 32 KB
    const int l = tid & 31, wid = tid >> 5;

#pragma unroll
    for (int i = 0; i < 8; i++) {
        int f4 = tid + i * 256;
        reinterpret_cast<float4*>(&sWg[0][0])[f4] =
            reinterpret_cast<const float4*>(Wg)[f4];
    }
    __syncthreads();

    const int t0 = blockIdx.x * 32 + wid * 4;
    float acc[4][N_EXP];
#pragma unroll
    for (int t = 0; t < 4; t++)
#pragma unroll
        for (int e = 0; e < N_EXP; e++) acc[t][e] = 0.f;

#pragma unroll
    for (int i = 0; i < 8; i++) {
        const int k = i * 128 + l * 4;
        float4 wv[N_EXP];
#pragma unroll
        for (int e = 0; e < N_EXP; e++)
            wv[e] = *reinterpret_cast<const float4*>(&sWg[e][k]);
#pragma unroll
        for (int t = 0; t < 4; t++) {
            float4 xv = *reinterpret_cast<const float4*>(x + (size_t)(t0 + t) * D_MODEL + k);
            uint2 u;
            u.x = h2u(__floats2half2_rn(xv.x, xv.y));
            u.y = h2u(__floats2half2_rn(xv.z, xv.w));
            *reinterpret_cast<uint2*>(g_xe + (size_t)(t0 + t) * K2 + k) = u;
#pragma unroll
            for (int e = 0; e < N_EXP; e++) {
                acc[t][e] = fmaf(xv.x, wv[e].x, acc[t][e]);
                acc[t][e] = fmaf(xv.y, wv[e].y, acc[t][e]);
                acc[t][e] = fmaf(xv.z, wv[e].z, acc[t][e]);
                acc[t][e] = fmaf(xv.w, wv[e].w, acc[t][e]);
            }
        }
    }

#pragma unroll
    for (int o = 16; o; o >>= 1)
#pragma unroll
        for (int t = 0; t < 4; t++)
#pragma unroll
            for (int e = 0; e < N_EXP; e++)
                acc[t][e] += __shfl_xor_sync(0xffffffffu, acc[t][e], o);

    if (l == 0) {
#pragma unroll
        for (int t = 0; t < 4; t++) {
            float* lg = acc[t];
            int i0 = 0; float v0 = lg[0];
#pragma unroll
            for (int e = 1; e < N_EXP; e++) if (lg[e] > v0) { v0 = lg[e]; i0 = e; }
            int i1 = -1; float v1 = -1e30f;
#pragma unroll
            for (int e = 0; e < N_EXP; e++) if (e != i0 && lg[e] > v1) { v1 = lg[e]; i1 = e; }
            float e1 = expf(v1 - v0);
            float inv = 1.0f / (1.0f + e1);
#pragma unroll
            for (int e = 0; e < N_EXP; e++)
                g_c[(size_t)(t0 + t) * N_EXP + e] = (e == i0) ? inv : (e == i1) ? e1 * inv : 0.f;
        }
    }
}

// ---------------------------------------------------------------------------
// gemm_h v3: h[8192,128] = xe[:, :1024] @ A^T ; epilogue *combine -> fp16 -> xe[:,1024:]
// CTA 64x128 (grid 128 -> halved A^T broadcast), 256 threads, 8 warps (2M x 4N,
// warp tile 32x32), BK=64, 3-stage.
// ---------------------------------------------------------------------------
#define HST_A 8192u                   // 64*64*2
#define HST_B 16384u                  // 128*64*2
#define HST   (HST_A + HST_B)         // 24576
#define H_SMEM (3 * HST)              // 73728

__global__ __launch_bounds__(256, 2)
void gemm_h() {
    extern __shared__ __align__(16) char hs[];
    const uint32_t s0 = smem_u32(hs);
    const int tid = threadIdx.x, l = tid & 31, wid = tid >> 5;
    const int wm = wid >> 2, wn = wid & 3;       // 2M x 4N of 32x32
    const int m0 = blockIdx.x * 64;

    float acc[2][4][4];
#pragma unroll
    for (int i = 0; i < 2; i++)
#pragma unroll
        for (int j = 0; j < 4; j++)
#pragma unroll
            for (int k = 0; k < 4; k++) acc[i][j][k] = 0.f;

    auto load_tile = [&](int st, int kt) {
        const uint32_t base = s0 + st * HST;
#pragma unroll
        for (int p = 0; p < 2; p++) {   // A: 64 rows x 8 chunks = 512 cp16
            int cid = tid + p * 256;
            int r = cid >> 3, c = cid & 7;
            cp16(base + SW64(r, c), g_xe + (size_t)(m0 + r) * K2 + kt + c * 8);
        }
#pragma unroll
        for (int p = 0; p < 4; p++) {   // B: 128 rows x 8 chunks = 1024 cp16
            int cid = tid + p * 256;
            int r = cid >> 3, c = cid & 7;
            cp16(base + HST_A + SW64(r, c), g_at + (size_t)r * D_MODEL + kt + c * 8);
        }
    };

    load_tile(0, 0); cp_commit();
    load_tile(1, 64); cp_commit();

    const int NIT = D_MODEL / 64;       // 16
    for (int it = 0; it < NIT; it++) {
        const int st = it % 3;
        if (it == NIT - 1) cp_wait<0>(); else cp_wait<1>();
        __syncthreads();
        if (it + 2 < NIT) { load_tile((it + 2) % 3, (it + 2) * 64); cp_commit(); }

        const uint32_t aBase = s0 + st * HST;
        const uint32_t bBase = aBase + HST_A;
#pragma unroll
        for (int ks = 0; ks < 4; ks++) {
            uint32_t af[2][4];
#pragma unroll
            for (int mt = 0; mt < 2; mt++) {
                int row = wm * 32 + mt * 16 + (l & 15);
                int ch = ks * 2 + (l >> 4);
                ldm4(af[mt], aBase + SW64(row, ch));
            }
#pragma unroll
            for (int q = 0; q < 2; q++) {
                uint32_t bf[4];
                int rn = wn * 32 + q * 16 + ((l >> 4) << 3) + (l & 7);
                int ch = ks * 2 + ((l >> 3) & 1);
                ldm4(bf, bBase + SW64(rn, ch));
#pragma unroll
                for (int mt = 0; mt < 2; mt++) {
                    mma16816(acc[mt][q * 2],     af[mt], bf);
                    mma16816(acc[mt][q * 2 + 1], af[mt], bf + 2);
                }
            }
        }
        __syncthreads();
    }

    // epilogue: scale by combine weight, fp16, store into xe[:, 1024+j]
#pragma unroll
    for (int mt = 0; mt < 2; mt++) {
        int r0 = m0 + wm * 32 + mt * 16 + (l >> 2);
#pragma unroll
        for (int nt = 0; nt < 4; nt++) {
            int j = wn * 32 + nt * 8 + (l & 3) * 2;
            int e = j >> 4;
            float* a4 = acc[mt][nt];
            float s0v = g_c[(size_t)r0 * N_EXP + e];
            float s1v = g_c[(size_t)(r0 + 8) * N_EXP + e];
            __half2 h0 = __floats2half2_rn(a4[0] * s0v, a4[1] * s0v);
            __half2 h1 = __floats2half2_rn(a4[2] * s1v, a4[3] * s1v);
            *reinterpret_cast<uint32_t*>(g_xe + (size_t)r0 * K2 + D_MODEL + j) = h2u(h0);
            *reinterpret_cast<uint32_t*>(g_xe + (size_t)(r0 + 8) * K2 + D_MODEL + j) = h2u(h1);
        }
    }
}

// ---------------------------------------------------------------------------
// gemm_main: out[8192,1024] = xe @ W2^T + bias.  (unchanged from R11)
// CTA 128x128, 128 threads (4 warps, warp tile 64x64), BK=64, 3-stage, 2 CTA/SM.
// ---------------------------------------------------------------------------
#define MST_A 16384u                  // 128*64*2
#define MST_B 16384u
#define MST   (MST_A + MST_B)         // 32768
#define MAIN_SMEM (3 * MST)           // 98304

__global__ __launch_bounds__(128, 2)
void gemm_main(const float* __restrict__ b_base, float* __restrict__ out) {
    extern __shared__ __align__(16) char ms[];
    const uint32_t s0 = smem_u32(ms);
    const int tid = threadIdx.x, l = tid & 31, wid = tid >> 5;
    const int wm = wid >> 1, wn = wid & 1;          // 2x2 warp grid, 64x64 tiles
    const int m0 = blockIdx.y * 128, n0 = blockIdx.x * 128;

    float acc[4][8][4];
#pragma unroll
    for (int i = 0; i < 4; i++)
#pragma unroll
        for (int j = 0; j < 8; j++)
#pragma unroll
            for (int k = 0; k < 4; k++) acc[i][j][k] = 0.f;

    auto load_tile = [&](int st, int kt) {
        const uint32_t base = s0 + st * MST;
#pragma unroll
        for (int p = 0; p < 8; p++) {
            int cid = tid + p * 128;
            int r = cid >> 3, c = cid & 7;
            cp16(base + SW64(r, c), g_xe + (size_t)(m0 + r) * K2 + kt + c * 8);
        }
#pragma unroll
        for (int p = 0; p < 8; p++) {
            int cid = tid + p * 128;
            int r = cid >> 3, c = cid & 7;
            cp16(base + MST_A + SW64(r, c), g_w2 + (size_t)(n0 + r) * K2 + kt + c * 8);
        }
    };

    load_tile(0, 0); cp_commit();
    load_tile(1, 64); cp_commit();

    const int NIT = K2 / 64;            // 18
    for (int it = 0; it < NIT; it++) {
        const int st = it % 3;
        if (it == NIT - 1) cp_wait<0>(); else cp_wait<1>();
        __syncthreads();
        if (it + 2 < NIT) { load_tile((it + 2) % 3, (it + 2) * 64); cp_commit(); }

        const uint32_t aBase = s0 + st * MST;
        const uint32_t bBase = aBase + MST_A;
#pragma unroll
        for (int ks = 0; ks < 4; ks++) {
            uint32_t af[4][4];
#pragma unroll
            for (int mt = 0; mt < 4; mt++) {
                int row = wm * 64 + mt * 16 + (l & 15);
                int ch = ks * 2 + (l >> 4);
                ldm4(af[mt], aBase + SW64(row, ch));
            }
            uint32_t bf[4][4];
#pragma unroll
            for (int q = 0; q < 4; q++) {
                int rn = wn * 64 + q * 16 + ((l >> 4) << 3) + (l & 7);
                int ch = ks * 2 + ((l >> 3) & 1);
                ldm4(bf[q], bBase + SW64(rn, ch));
            }
#pragma unroll
            for (int mt = 0; mt < 4; mt++)
#pragma unroll
                for (int q = 0; q < 4; q++) {
                    mma16816(acc[mt][q * 2],     af[mt], bf[q]);
                    mma16816(acc[mt][q * 2 + 1], af[mt], bf[q] + 2);
                }
        }
        __syncthreads();
    }

    // epilogue: + bias, write-only
#pragma unroll
    for (int mt = 0; mt < 4; mt++) {
        int r0 = m0 + wm * 64 + mt * 16 + (l >> 2);
#pragma unroll
        for (int nt = 0; nt < 8; nt++) {
            int j = n0 + wn * 64 + nt * 8 + (l & 3) * 2;
            float* a4 = acc[mt][nt];
            float2 bb = *reinterpret_cast<const float2*>(b_base + j);
            *reinterpret_cast<float2*>(out + (size_t)r0 * D_MODEL + j) =
                make_float2(a4[0] + bb.x, a4[1] + bb.y);
            *reinterpret_cast<float2*>(out + (size_t)(r0 + 8) * D_MODEL + j) =
                make_float2(a4[2] + bb.x, a4[3] + bb.y);
        }
    }
}

// ---------------------------------------------------------------------------
extern "C" void kernel_launch(void* const* d_in, const int* in_sizes, int n_in,
                              void* d_out, int out_size) {
    const float* x      = (const float*)d_in[0];
    const float* W_gate = (const float*)d_in[1];
    const float* A      = (const float*)d_in[2];
    const float* Bmat   = (const float*)d_in[3];
    const float* W_base = (const float*)d_in[4];
    const float* b_base = (const float*)d_in[5];
    float* out = (float*)d_out;

    cudaFuncSetAttribute(gemm_h, cudaFuncAttributeMaxDynamicSharedMemorySize, H_SMEM);
    cudaFuncSetAttribute(gemm_main, cudaFuncAttributeMaxDynamicSharedMemorySize, MAIN_SMEM);

    pack_all<<<GATE_BLOCKS + WPACK_BLOCKS, 256>>>(x, W_gate, W_base, Bmat, A);

    gemm_h<<<N_TOK / 64, 256, H_SMEM>>>();

    gemm_main<<<dim3(D_MODEL / 128, N_TOK / 128), 128, MAIN_SMEM>>>(b_base, out);
}

// round 14
// speedup vs baseline: 1.0526x; 1.0526x over previous
#include <cuda_runtime.h>
#include <cuda_fp16.h>
#include <cstdint>
#include <math.h>

#define N_TOK   8192
#define D_MODEL 1024
#define N_EXP   8
#define RANK    16
#define H_COLS  128
#define K2      (D_MODEL + H_COLS)   // 1152 concatenated K

// ---------------- device scratch (no-alloc rule) ----------------
__device__ __align__(16) __half g_xe[N_TOK * K2];        // [x | c*h] fp16, row stride 1152
__device__ __align__(16) __half g_w2[D_MODEL * K2];      // [Wbase^T ; B] fp16: row d, col k
__device__ __align__(16) __half g_at[H_COLS * D_MODEL];  // A^T fp16: [er][d]
__device__ __align__(16) float  g_c[N_TOK * N_EXP];      // dense combine weights

// ---------------- asm helpers (legal at compute_103) ----------------
__device__ __forceinline__ uint32_t smem_u32(const void* p) {
    uint32_t a;
    asm("{ .reg .u64 t; cvta.to.shared.u64 t, %1; cvt.u32.u64 %0, t; }" : "=r"(a) : "l"(p));
    return a;
}
__device__ __forceinline__ void cp16(uint32_t s, const void* g) {
    asm volatile("cp.async.cg.shared.global [%0], [%1], 16;" :: "r"(s), "l"(g));
}
__device__ __forceinline__ void cp_commit() {
    asm volatile("cp.async.commit_group;" ::: "memory");
}
template<int N> __device__ __forceinline__ void cp_wait() {
    asm volatile("cp.async.wait_group %0;" :: "n"(N) : "memory");
}
__device__ __forceinline__ void ldm4(uint32_t (&r)[4], uint32_t a) {
    asm volatile("ldmatrix.sync.aligned.m8n8.x4.shared.b16 {%0,%1,%2,%3}, [%4];"
        : "=r"(r[0]), "=r"(r[1]), "=r"(r[2]), "=r"(r[3]) : "r"(a));
}
__device__ __forceinline__ void mma16816(float* c, const uint32_t* a, const uint32_t* b) {
    asm volatile("mma.sync.aligned.m16n8k16.row.col.f32.f16.f16.f32 "
        "{%0,%1,%2,%3}, {%4,%5,%6,%7}, {%8,%9}, {%0,%1,%2,%3};"
        : "+f"(c[0]), "+f"(c[1]), "+f"(c[2]), "+f"(c[3])
        : "r"(a[0]), "r"(a[1]), "r"(a[2]), "r"(a[3]), "r"(b[0]), "r"(b[1]));
}
__device__ __forceinline__ uint32_t h2u(__half2 h) { return *reinterpret_cast<uint32_t*>(&h); }

// 128B-row swizzle (64 halves/row, 8 x 16B chunks): chunk' = c ^ (r&7)
#define SW64(r, c) ((uint32_t)((r) * 128 + (((c) ^ ((r) & 7)) << 4)))

// ---------------------------------------------------------------------------
// Fused pack x -> fp16 (into xe[:,0:1024]) + fp32 gate -> dense combine g_c
// ---------------------------------------------------------------------------
__global__ __launch_bounds__(256)
void pack_gate(const float* __restrict__ x, const float* __restrict__ Wg) {
    __shared__ float sWg[N_EXP][D_MODEL];          // 32 KB
    const int tid = threadIdx.x, l = tid & 31, wid = tid >> 5;

#pragma unroll
    for (int i = 0; i < 8; i++) {
        int f4 = tid + i * 256;
        reinterpret_cast<float4*>(&sWg[0][0])[f4] =
            reinterpret_cast<const float4*>(Wg)[f4];
    }
    __syncthreads();

    const int t0 = blockIdx.x * 32 + wid * 4;
    float acc[4][N_EXP];
#pragma unroll
    for (int t = 0; t < 4; t++)
#pragma unroll
        for (int e = 0; e < N_EXP; e++) acc[t][e] = 0.f;

#pragma unroll
    for (int i = 0; i < 8; i++) {
        const int k = i * 128 + l * 4;
        float4 wv[N_EXP];
#pragma unroll
        for (int e = 0; e < N_EXP; e++)
            wv[e] = *reinterpret_cast<const float4*>(&sWg[e][k]);
#pragma unroll
        for (int t = 0; t < 4; t++) {
            float4 xv = *reinterpret_cast<const float4*>(x + (size_t)(t0 + t) * D_MODEL + k);
            uint2 u;
            u.x = h2u(__floats2half2_rn(xv.x, xv.y));
            u.y = h2u(__floats2half2_rn(xv.z, xv.w));
            *reinterpret_cast<uint2*>(g_xe + (size_t)(t0 + t) * K2 + k) = u;
#pragma unroll
            for (int e = 0; e < N_EXP; e++) {
                acc[t][e] = fmaf(xv.x, wv[e].x, acc[t][e]);
                acc[t][e] = fmaf(xv.y, wv[e].y, acc[t][e]);
                acc[t][e] = fmaf(xv.z, wv[e].z, acc[t][e]);
                acc[t][e] = fmaf(xv.w, wv[e].w, acc[t][e]);
            }
        }
    }

#pragma unroll
    for (int o = 16; o; o >>= 1)
#pragma unroll
        for (int t = 0; t < 4; t++)
#pragma unroll
            for (int e = 0; e < N_EXP; e++)
                acc[t][e] += __shfl_xor_sync(0xffffffffu, acc[t][e], o);

    if (l == 0) {
#pragma unroll
        for (int t = 0; t < 4; t++) {
            float* lg = acc[t];
            int i0 = 0; float v0 = lg[0];
#pragma unroll
            for (int e = 1; e < N_EXP; e++) if (lg[e] > v0) { v0 = lg[e]; i0 = e; }
            int i1 = -1; float v1 = -1e30f;
#pragma unroll
            for (int e = 0; e < N_EXP; e++) if (e != i0 && lg[e] > v1) { v1 = lg[e]; i1 = e; }
            float e1 = expf(v1 - v0);
            float inv = 1.0f / (1.0f + e1);
#pragma unroll
            for (int e = 0; e < N_EXP; e++)
                g_c[(size_t)(t0 + t) * N_EXP + e] = (e == i0) ? inv : (e == i1) ? e1 * inv : 0.f;
        }
    }
}

// ---------------------------------------------------------------------------
// Weight pack (separate lightweight kernel — full occupancy, no smem)
// ---------------------------------------------------------------------------
#define W2_ELEMS (D_MODEL * K2)
#define AT_ELEMS (H_COLS * D_MODEL)
__global__ void pack_weights(const float* __restrict__ Wb, const float* __restrict__ Bmat,
                             const float* __restrict__ A) {
    int idx = blockIdx.x * blockDim.x + threadIdx.x;
    if (idx < W2_ELEMS) {
        int d = idx / K2, k = idx - d * K2;
        float v = (k < D_MODEL) ? Wb[(size_t)d * D_MODEL + k]
                                : Bmat[(size_t)(k - D_MODEL) * D_MODEL + d];
        g_w2[idx] = __float2half_rn(v);
    } else if (idx < W2_ELEMS + AT_ELEMS) {
        int t = idx - W2_ELEMS;
        int er = t >> 10, d = t & 1023;
        int e = er >> 4, r = er & 15;
        g_at[t] = __float2half_rn(A[((size_t)e * D_MODEL + d) * RANK + r]);
    }
}

// ---------------------------------------------------------------------------
// gemm_h v3: h[8192,128] = xe[:, :1024] @ A^T ; epilogue *combine -> fp16 -> xe[:,1024:]
// CTA 64x128 (grid 128 -> halved A^T broadcast), 256 threads, 8 warps (2M x 4N,
// warp tile 32x32), BK=64, 3-stage.
// ---------------------------------------------------------------------------
#define HST_A 8192u                   // 64*64*2
#define HST_B 16384u                  // 128*64*2
#define HST   (HST_A + HST_B)         // 24576
#define H_SMEM (3 * HST)              // 73728

__global__ __launch_bounds__(256, 2)
void gemm_h() {
    extern __shared__ __align__(16) char hs[];
    const uint32_t s0 = smem_u32(hs);
    const int tid = threadIdx.x, l = tid & 31, wid = tid >> 5;
    const int wm = wid >> 2, wn = wid & 3;       // 2M x 4N of 32x32
    const int m0 = blockIdx.x * 64;

    float acc[2][4][4];
#pragma unroll
    for (int i = 0; i < 2; i++)
#pragma unroll
        for (int j = 0; j < 4; j++)
#pragma unroll
            for (int k = 0; k < 4; k++) acc[i][j][k] = 0.f;

    auto load_tile = [&](int st, int kt) {
        const uint32_t base = s0 + st * HST;
#pragma unroll
        for (int p = 0; p < 2; p++) {   // A: 64 rows x 8 chunks = 512 cp16
            int cid = tid + p * 256;
            int r = cid >> 3, c = cid & 7;
            cp16(base + SW64(r, c), g_xe + (size_t)(m0 + r) * K2 + kt + c * 8);
        }
#pragma unroll
        for (int p = 0; p < 4; p++) {   // B: 128 rows x 8 chunks = 1024 cp16
            int cid = tid + p * 256;
            int r = cid >> 3, c = cid & 7;
            cp16(base + HST_A + SW64(r, c), g_at + (size_t)r * D_MODEL + kt + c * 8);
        }
    };

    load_tile(0, 0); cp_commit();
    load_tile(1, 64); cp_commit();

    const int NIT = D_MODEL / 64;       // 16
    for (int it = 0; it < NIT; it++) {
        const int st = it % 3;
        if (it == NIT - 1) cp_wait<0>(); else cp_wait<1>();
        __syncthreads();
        if (it + 2 < NIT) { load_tile((it + 2) % 3, (it + 2) * 64); cp_commit(); }

        const uint32_t aBase = s0 + st * HST;
        const uint32_t bBase = aBase + HST_A;
#pragma unroll
        for (int ks = 0; ks < 4; ks++) {
            uint32_t af[2][4];
#pragma unroll
            for (int mt = 0; mt < 2; mt++) {
                int row = wm * 32 + mt * 16 + (l & 15);
                int ch = ks * 2 + (l >> 4);
                ldm4(af[mt], aBase + SW64(row, ch));
            }
#pragma unroll
            for (int q = 0; q < 2; q++) {
                uint32_t bf[4];
                int rn = wn * 32 + q * 16 + ((l >> 4) << 3) + (l & 7);
                int ch = ks * 2 + ((l >> 3) & 1);
                ldm4(bf, bBase + SW64(rn, ch));
#pragma unroll
                for (int mt = 0; mt < 2; mt++) {
                    mma16816(acc[mt][q * 2],     af[mt], bf);
                    mma16816(acc[mt][q * 2 + 1], af[mt], bf + 2);
                }
            }
        }
        __syncthreads();
    }

    // epilogue: scale by combine weight, fp16, store into xe[:, 1024+j]
#pragma unroll
    for (int mt = 0; mt < 2; mt++) {
        int r0 = m0 + wm * 32 + mt * 16 + (l >> 2);
#pragma unroll
        for (int nt = 0; nt < 4; nt++) {
            int j = wn * 32 + nt * 8 + (l & 3) * 2;
            int e = j >> 4;
            float* a4 = acc[mt][nt];
            float s0v = g_c[(size_t)r0 * N_EXP + e];
            float s1v = g_c[(size_t)(r0 + 8) * N_EXP + e];
            __half2 h0 = __floats2half2_rn(a4[0] * s0v, a4[1] * s0v);
            __half2 h1 = __floats2half2_rn(a4[2] * s1v, a4[3] * s1v);
            *reinterpret_cast<uint32_t*>(g_xe + (size_t)r0 * K2 + D_MODEL + j) = h2u(h0);
            *reinterpret_cast<uint32_t*>(g_xe + (size_t)(r0 + 8) * K2 + D_MODEL + j) = h2u(h1);
        }
    }
}

// ---------------------------------------------------------------------------
// gemm_main: out[8192,1024] = xe @ W2^T + bias.  (unchanged from R11)
// CTA 128x128, 128 threads (4 warps, warp tile 64x64), BK=64, 3-stage, 2 CTA/SM.
// ---------------------------------------------------------------------------
#define MST_A 16384u                  // 128*64*2
#define MST_B 16384u
#define MST   (MST_A + MST_B)         // 32768
#define MAIN_SMEM (3 * MST)           // 98304

__global__ __launch_bounds__(128, 2)
void gemm_main(const float* __restrict__ b_base, float* __restrict__ out) {
    extern __shared__ __align__(16) char ms[];
    const uint32_t s0 = smem_u32(ms);
    const int tid = threadIdx.x, l = tid & 31, wid = tid >> 5;
    const int wm = wid >> 1, wn = wid & 1;          // 2x2 warp grid, 64x64 tiles
    const int m0 = blockIdx.y * 128, n0 = blockIdx.x * 128;

    float acc[4][8][4];
#pragma unroll
    for (int i = 0; i < 4; i++)
#pragma unroll
        for (int j = 0; j < 8; j++)
#pragma unroll
            for (int k = 0; k < 4; k++) acc[i][j][k] = 0.f;

    auto load_tile = [&](int st, int kt) {
        const uint32_t base = s0 + st * MST;
#pragma unroll
        for (int p = 0; p < 8; p++) {
            int cid = tid + p * 128;
            int r = cid >> 3, c = cid & 7;
            cp16(base + SW64(r, c), g_xe + (size_t)(m0 + r) * K2 + kt + c * 8);
        }
#pragma unroll
        for (int p = 0; p < 8; p++) {
            int cid = tid + p * 128;
            int r = cid >> 3, c = cid & 7;
            cp16(base + MST_A + SW64(r, c), g_w2 + (size_t)(n0 + r) * K2 + kt + c * 8);
        }
    };

    load_tile(0, 0); cp_commit();
    load_tile(1, 64); cp_commit();

    const int NIT = K2 / 64;            // 18
    for (int it = 0; it < NIT; it++) {
        const int st = it % 3;
        if (it == NIT - 1) cp_wait<0>(); else cp_wait<1>();
        __syncthreads();
        if (it + 2 < NIT) { load_tile((it + 2) % 3, (it + 2) * 64); cp_commit(); }

        const uint32_t aBase = s0 + st * MST;
        const uint32_t bBase = aBase + MST_A;
#pragma unroll
        for (int ks = 0; ks < 4; ks++) {
            uint32_t af[4][4];
#pragma unroll
            for (int mt = 0; mt < 4; mt++) {
                int row = wm * 64 + mt * 16 + (l & 15);
                int ch = ks * 2 + (l >> 4);
                ldm4(af[mt], aBase + SW64(row, ch));
            }
            uint32_t bf[4][4];
#pragma unroll
            for (int q = 0; q < 4; q++) {
                int rn = wn * 64 + q * 16 + ((l >> 4) << 3) + (l & 7);
                int ch = ks * 2 + ((l >> 3) & 1);
                ldm4(bf[q], bBase + SW64(rn, ch));
            }
#pragma unroll
            for (int mt = 0; mt < 4; mt++)
#pragma unroll
                for (int q = 0; q < 4; q++) {
                    mma16816(acc[mt][q * 2],     af[mt], bf[q]);
                    mma16816(acc[mt][q * 2 + 1], af[mt], bf[q] + 2);
                }
        }
        __syncthreads();
    }

    // epilogue: + bias, write-only
#pragma unroll
    for (int mt = 0; mt < 4; mt++) {
        int r0 = m0 + wm * 64 + mt * 16 + (l >> 2);
#pragma unroll
        for (int nt = 0; nt < 8; nt++) {
            int j = n0 + wn * 64 + nt * 8 + (l & 3) * 2;
            float* a4 = acc[mt][nt];
            float2 bb = *reinterpret_cast<const float2*>(b_base + j);
            *reinterpret_cast<float2*>(out + (size_t)r0 * D_MODEL + j) =
                make_float2(a4[0] + bb.x, a4[1] + bb.y);
            *reinterpret_cast<float2*>(out + (size_t)(r0 + 8) * D_MODEL + j) =
                make_float2(a4[2] + bb.x, a4[3] + bb.y);
        }
    }
}

// ---------------------------------------------------------------------------
extern "C" void kernel_launch(void* const* d_in, const int* in_sizes, int n_in,
                              void* d_out, int out_size) {
    const float* x      = (const float*)d_in[0];
    const float* W_gate = (const float*)d_in[1];
    const float* A      = (const float*)d_in[2];
    const float* Bmat   = (const float*)d_in[3];
    const float* W_base = (const float*)d_in[4];
    const float* b_base = (const float*)d_in[5];
    float* out = (float*)d_out;

    cudaFuncSetAttribute(gemm_h, cudaFuncAttributeMaxDynamicSharedMemorySize, H_SMEM);
    cudaFuncSetAttribute(gemm_main, cudaFuncAttributeMaxDynamicSharedMemorySize, MAIN_SMEM);

    pack_gate<<<N_TOK / 32, 256>>>(x, W_gate);
    pack_weights<<<(W2_ELEMS + AT_ELEMS + 255) / 256, 256>>>(W_base, Bmat, A);

    gemm_h<<<N_TOK / 64, 256, H_SMEM>>>();

    gemm_main<<<dim3(D_MODEL / 128, N_TOK / 128), 128, MAIN_SMEM>>>(b_base, out);
}